// round 15
// baseline (speedup 1.0000x reference)
#include <cuda_runtime.h>
#include <math.h>

typedef unsigned long long ull;

// Problem constants
#define S_   256
#define B_   2
#define HID_ 512
#define NH_  8
#define HD_  64
#define NCH_ 2048

// ---------------- scratch ----------------------------------------------------
__device__ float g_mx  [4][3 * B_ * S_ * HID_];  // K-split partials (4)
__device__ float g_lin [2 * B_ * S_ * HID_];     // ql, kl only
__device__ float g_gv  [B_ * NCH_ * HD_];        // gamma * vl
__device__ float g_qn2 [B_ * NCH_];
__device__ float g_kl2 [B_ * NCH_];
__device__ float g_gamma[B_ * NCH_];
__device__ float g_probs[B_ * NH_ * S_ * S_];    // fallback if out has no room
__device__ float g_part[8][B_ * NH_ * S_ * 68];  // midpoint partials: 64 nom + den@64
__device__ float g_dummy[32];                    // prep_kernel sink

// ---------------- f32x2 packed helpers ---------------------------------------
#define FMA2(d, a, b, c) \
    asm("fma.rn.f32x2 %0, %1, %2, %3;" : "=l"(d) : "l"(a), "l"(b), "l"(c))
#define MUL2(d, a, b) \
    asm("mul.rn.f32x2 %0, %1, %2;" : "=l"(d) : "l"(a), "l"(b))
#define ADD2(d, a, b) \
    asm("add.rn.f32x2 %0, %1, %2;" : "=l"(d) : "l"(a), "l"(b))
#define PK2(d, lo, hi) \
    asm("mov.b64 %0, {%1, %2};" : "=l"(d) : "f"(lo), "f"(hi))
#define UPK2(lo, hi, s) \
    asm("mov.b64 {%0, %1}, %2;" : "=f"(lo), "=f"(hi) : "l"(s))

__device__ __forceinline__ float frcp(float x) {
    float r; asm("rcp.approx.f32 %0, %1;" : "=f"(r) : "f"(x)); return r;
}

__device__ __forceinline__ float artanh_pos(float x) {
    x = fminf(x, 1.f - 1e-7f);
    return 0.5f * __logf((1.f + x) / (1.f - x));
}

__device__ __forceinline__ float warp_sum(float v) {
#pragma unroll
    for (int o = 16; o; o >>= 1) v += __shfl_xor_sync(0xffffffffu, v, o);
    return v;
}

__device__ __forceinline__ float dot4(float4 a, float4 b) {
    return a.x * b.x + a.y * b.y + a.z * b.z + a.w * b.w;
}

// ---------------- K0: trivial prep (shifts scores into profiled slot 4) ------
__global__ void prep_kernel()
{
    if (threadIdx.x < 32) g_dummy[threadIdx.x] = (float)threadIdx.x;
}

// ---------------- K1: MX = X @ W^T -------------------------------------------
// 64x128 tile, 4q x 8i register blocking, K-split 4, register prefetch.
// grid (12, 8, 4), 256 threads.  (R12 measured-best config)
__global__ __launch_bounds__(256) void gemm_kernel(
    const float* __restrict__ qin, const float* __restrict__ Wq,
    const float* __restrict__ Wk,  const float* __restrict__ Wv)
{
    __shared__ __align__(16) float Xs[16][64];
    __shared__ __align__(16) float Ws[16][128];

    int bx = blockIdx.x, by = blockIdx.y, ks = blockIdx.z;
    int t  = threadIdx.x;
    int tx = t & 15, ty = t >> 4;

    int m = bx >> 2;
    const float* W = (m == 0) ? Wq : (m == 1) ? Wk : Wv;
    int ibase = (bx & 3) * 128;

    int lr = t >> 2;           // 0..63 (X row)
    int lk = (t & 3) * 4;      // 0,4,8,12
    int wr = t >> 1;           // 0..127 (W row / out col)
    int wk = (t & 1) * 8;      // 0,8

    int grow = by * 64 + lr;
    int gb = grow >> 8, gs = grow & 255;
    const float* xptr = qin + (gs * 2 + gb) * 512 + lk;
    const float* wptr = W + (ibase + wr) * 512 + wk;

    ull acc[4][4];
#pragma unroll
    for (int i = 0; i < 4; i++)
#pragma unroll
        for (int j = 0; j < 4; j++) acc[i][j] = 0ull;

    int k0beg = ks * 128, k0end = k0beg + 128;
    float4 xv  = *(const float4*)(xptr + k0beg);
    float4 wv0 = *(const float4*)(wptr + k0beg);
    float4 wv1 = *(const float4*)(wptr + k0beg + 4);

    for (int k0 = k0beg; k0 < k0end; k0 += 16) {
        Xs[lk + 0][lr] = xv.x; Xs[lk + 1][lr] = xv.y;
        Xs[lk + 2][lr] = xv.z; Xs[lk + 3][lr] = xv.w;
        Ws[wk + 0][wr] = wv0.x; Ws[wk + 1][wr] = wv0.y;
        Ws[wk + 2][wr] = wv0.z; Ws[wk + 3][wr] = wv0.w;
        Ws[wk + 4][wr] = wv1.x; Ws[wk + 5][wr] = wv1.y;
        Ws[wk + 6][wr] = wv1.z; Ws[wk + 7][wr] = wv1.w;
        __syncthreads();
        if (k0 + 16 < k0end) {               // register prefetch of next stage
            xv  = *(const float4*)(xptr + k0 + 16);
            wv0 = *(const float4*)(wptr + k0 + 16);
            wv1 = *(const float4*)(wptr + k0 + 20);
        }
#pragma unroll
        for (int kk = 0; kk < 16; kk++) {
            float4 a = *(const float4*)&Xs[kk][ty * 4];
            ulonglong2 b0 = *(const ulonglong2*)&Ws[kk][tx * 4];
            ulonglong2 b1 = *(const ulonglong2*)&Ws[kk][64 + tx * 4];
            ull aii;
            PK2(aii, a.x, a.x);
            FMA2(acc[0][0], aii, b0.x, acc[0][0]); FMA2(acc[0][1], aii, b0.y, acc[0][1]);
            FMA2(acc[0][2], aii, b1.x, acc[0][2]); FMA2(acc[0][3], aii, b1.y, acc[0][3]);
            PK2(aii, a.y, a.y);
            FMA2(acc[1][0], aii, b0.x, acc[1][0]); FMA2(acc[1][1], aii, b0.y, acc[1][1]);
            FMA2(acc[1][2], aii, b1.x, acc[1][2]); FMA2(acc[1][3], aii, b1.y, acc[1][3]);
            PK2(aii, a.z, a.z);
            FMA2(acc[2][0], aii, b0.x, acc[2][0]); FMA2(acc[2][1], aii, b0.y, acc[2][1]);
            FMA2(acc[2][2], aii, b1.x, acc[2][2]); FMA2(acc[2][3], aii, b1.y, acc[2][3]);
            PK2(aii, a.w, a.w);
            FMA2(acc[3][0], aii, b0.x, acc[3][0]); FMA2(acc[3][1], aii, b0.y, acc[3][1]);
            FMA2(acc[3][2], aii, b1.x, acc[3][2]); FMA2(acc[3][3], aii, b1.y, acc[3][3]);
        }
        __syncthreads();
    }

    int row0 = by * 64 + ty * 4;
#pragma unroll
    for (int i = 0; i < 4; i++) {
        int row = row0 + i;
        int b = row >> 8, s = row & 255;
        float* orow = &g_mx[ks][(((m * 2 + b) * 256 + s) * 512)];
        float4 v0, v1;
        UPK2(v0.x, v0.y, acc[i][0]); UPK2(v0.z, v0.w, acc[i][1]);
        UPK2(v1.x, v1.y, acc[i][2]); UPK2(v1.z, v1.w, acc[i][3]);
        *(float4*)&orow[ibase + tx * 4]      = v0;
        *(float4*)&orow[ibase + 64 + tx * 4] = v1;
    }
}

// ---------------- K2: manifold linear + logmap0 + chunk expmap0 ---------------
// warp-per-row: grid (64, 3), 256 threads. Lane l owns elems l*4+128j, j=0..3.
// m==2 (V) writes gamma*vl into g_gv and gamma into g_gamma.
__global__ __launch_bounds__(256) void postproc_kernel(
    const float* __restrict__ qin, const float* __restrict__ bq,
    const float* __restrict__ bk,  const float* __restrict__ bv)
{
    int t = threadIdx.x, w = t >> 5, l = t & 31;
    int r = blockIdx.x * 8 + w;         // 0..511
    int m = blockIdx.y;
    int b = r >> 8, s = r & 255;

    const float* xrow = qin + (s * 2 + b) * 512;
    size_t mxoff = (size_t)((m * 2 + b) * 256 + s) * 512;
    const float* bias = (m == 0) ? bq : (m == 1) ? bk : bv;

    float4 xv[4], mv[4], bb[4];
#pragma unroll
    for (int j = 0; j < 4; j++) {
        int e = l * 4 + 128 * j;
        xv[j] = *(const float4*)(xrow + e);
        float4 p0 = *(const float4*)&g_mx[0][mxoff + e];
        float4 p1 = *(const float4*)&g_mx[1][mxoff + e];
        float4 p2 = *(const float4*)&g_mx[2][mxoff + e];
        float4 p3 = *(const float4*)&g_mx[3][mxoff + e];
        mv[j] = make_float4((p0.x + p1.x) + (p2.x + p3.x),
                            (p0.y + p1.y) + (p2.y + p3.y),
                            (p0.z + p1.z) + (p2.z + p3.z),
                            (p0.w + p1.w) + (p2.w + p3.w));
        bb[j] = *(const float4*)(bias + e);
    }

    float sx = 0.f, smx = 0.f;
#pragma unroll
    for (int j = 0; j < 4; j++) { sx += dot4(xv[j], xv[j]); smx += dot4(mv[j], mv[j]); }
    sx = warp_sum(sx); smx = warp_sum(smx);

    float xn  = fmaxf(sqrtf(sx),  1e-15f);
    float mxn = fmaxf(sqrtf(smx), 1e-15f);
    float scm = tanhf((mxn / xn) * artanh_pos(xn)) / mxn;

    float xy = 0.f, x2 = 0.f, y2 = 0.f;
    float4 rv[4];
#pragma unroll
    for (int j = 0; j < 4; j++) {
        rv[j] = make_float4(scm * mv[j].x, scm * mv[j].y, scm * mv[j].z, scm * mv[j].w);
        xy += dot4(rv[j], bb[j]); x2 += dot4(rv[j], rv[j]); y2 += dot4(bb[j], bb[j]);
    }
    xy = warp_sum(xy); x2 = warp_sum(x2); y2 = warp_sum(y2);

    float ca = 1.f + 2.f * xy + y2;
    float cb = 1.f - x2;
    float den = fmaxf(1.f + 2.f * xy + x2 * y2, 1e-15f);
    float rd = __fdividef(1.f, den);

    float so = 0.f;
    float4 ov[4];
#pragma unroll
    for (int j = 0; j < 4; j++) {
        ov[j] = make_float4((ca * rv[j].x + cb * bb[j].x) * rd,
                            (ca * rv[j].y + cb * bb[j].y) * rd,
                            (ca * rv[j].z + cb * bb[j].z) * rd,
                            (ca * rv[j].w + cb * bb[j].w) * rd);
        so += dot4(ov[j], ov[j]);
    }
    so = warp_sum(so);
    float n = fmaxf(sqrtf(so), 1e-15f);
    float pf = (n > 0.996f) ? (0.996f / n) : 1.f;   // projx
    n = fminf(n, 0.996f);
    float ls = artanh_pos(n) / n * pf;              // logmap0 over HID (+proj)

    float* Lrow = g_lin + ((m * 2 + b) * 256 + s) * 512;
#pragma unroll
    for (int j = 0; j < 4; j++) {
        float4 uv = make_float4(ls * ov[j].x, ls * ov[j].y, ls * ov[j].z, ls * ov[j].w);
        float cu = dot4(uv, uv);
        cu += __shfl_xor_sync(0xffffffffu, cu, 1);
        cu += __shfl_xor_sync(0xffffffffu, cu, 2);
        cu += __shfl_xor_sync(0xffffffffu, cu, 4);
        cu += __shfl_xor_sync(0xffffffffu, cu, 8);   // sum over 16-lane group
        float cn = fmaxf(sqrtf(cu), 1e-15f);
        float es = tanhf(cn) / cn;                   // chunk expmap0
        float4 lv = make_float4(es * uv.x, es * uv.y, es * uv.z, es * uv.w);
        int c = (l >> 4) + 2 * j;                    // chunk within row
        int idx = b * NCH_ + s * 8 + c;              // flat (b, h*256+s2)
        if (m < 2) {
            *(float4*)(Lrow + l * 4 + 128 * j) = lv;
            if ((l & 15) == 0) {
                float st = es * es * cu;
                if (m == 0) g_qn2[idx] = st;
                else        g_kl2[idx] = st;
            }
        } else {
            float st = es * es * cu;                 // group-uniform
            float ga = 2.f / fmaxf(1.f - st, 1e-15f);
            *(float4*)&g_gv[(size_t)idx * 64 + (l & 15) * 4] =
                make_float4(ga * lv.x, ga * lv.y, ga * lv.z, ga * lv.w);
            if ((l & 15) == 0) g_gamma[idx] = ga;
        }
    }
}

// ---------------- K3: pairwise scores + sigmoid -------------------------------
// grid (32 qtiles of 8, 16 bh), 256 threads; thread = n, K-row in registers.
// num = Bc*(k - r*q), r = A/Bc; 4-way rcp combine with PACKED sum/product.
// minBlocksPerMultiprocessor=3 caps regs at ~85 (64 kr2 + working set) to lift
// occupancy from ~2 to 3+ blocks/SM.
__global__ __launch_bounds__(256, 3) void scores_kernel(float* __restrict__ pp)
{
    __shared__ __align__(16) float qs[8 * 64];
    __shared__ float q2s[8];

    int qt = blockIdx.x, bh = blockIdx.y;
    int base = bh * 256;
    int qg0 = qt * 8;
    int t = threadIdx.x;

    const float* gql = g_lin;
    const float* gkl = g_lin + B_ * S_ * HID_;

    for (int idx = t; idx < 8 * 64; idx += 256)
        qs[idx] = gql[(base + qg0) * 64 + idx];
    if (t < 8) q2s[t] = g_qn2[base + qg0 + t];

    ull kr2[32];
    {
        const float* krow = gkl + (base + t) * 64;
#pragma unroll
        for (int i = 0; i < 16; i++) {
            ulonglong2 v = *(const ulonglong2*)(krow + i * 4);
            kr2[2 * i]     = v.x;
            kr2[2 * i + 1] = v.y;
        }
    }
    float y2 = g_kl2[base + t];
    __syncthreads();

    float* prow = pp + (size_t)(bh * 256 + qg0) * 256 + t;

    for (int q = 0; q < 8; q++) {
        const ulonglong2* qr2 = (const ulonglong2*)&qs[q * 64];
        float x2 = q2s[q];

        // dot(q, k)
        ull a0 = 0ull, a1 = 0ull, a2 = 0ull, a3 = 0ull;
#pragma unroll
        for (int i = 0; i < 16; i += 2) {
            ulonglong2 qa = qr2[i];
            ulonglong2 qb = qr2[i + 1];
            FMA2(a0, kr2[2 * i],     qa.x, a0);
            FMA2(a1, kr2[2 * i + 1], qa.y, a1);
            FMA2(a2, kr2[2 * i + 2], qb.x, a2);
            FMA2(a3, kr2[2 * i + 3], qb.y, a3);
        }
        float s0, s1, s2, s3, s4, s5, s6, s7;
        UPK2(s0, s1, a0); UPK2(s2, s3, a1); UPK2(s4, s5, a2); UPK2(s6, s7, a3);
        float xy = ((s0 + s1) + (s2 + s3)) + ((s4 + s5) + (s6 + s7));

        float A  = 1.f - 2.f * xy + y2;
        float Bc = 1.f - x2;
        float den = fmaxf(1.f - 2.f * xy + x2 * y2, 1e-15f);
        float r = __fdividef(A, Bc);
        float fsc = __fdividef(den, Bc);
        fsc *= fsc;                                  // (den/Bc)^2

        ull nr2;
        PK2(nr2, -r, -r);

        // sum 1/(k - r*q)^2 via 4-way combine, groups (e0,e2) & (e1,e3):
        //   sv = sqa+sqb, pv = sqa*sqb (packed);
        //   sum = (sv.lo*pv.hi + sv.hi*pv.lo) / (pv.lo*pv.hi)
        float t0 = 0.f;
#pragma unroll
        for (int i = 0; i < 16; i++) {
            ulonglong2 qv = qr2[i];
            ull num, sqa, sqb, sv, pv;
            FMA2(num, nr2, qv.x, kr2[2 * i]);
            MUL2(sqa, num, num);
            FMA2(num, nr2, qv.y, kr2[2 * i + 1]);
            MUL2(sqb, num, num);
            ADD2(sv, sqa, sqb);
            MUL2(pv, sqa, sqb);
            float svl, svh, pvl, pvh;
            UPK2(svl, svh, sv);
            UPK2(pvl, pvh, pv);
            float num4 = fmaf(svl, pvh, svh * pvl);
            float den4 = fmaxf(pvl * pvh, 1e-37f);
            t0 = fmaf(num4, frcp(den4), t0);
        }
        float tacc = t0 * fsc;
        float tt = rsqrtf(tacc);
        float sc = -2.f * artanh_pos(tt);
        sc = fminf(fmaxf(sc, -1e10f), 1e10f);
        float p = __fdividef(1.f, 1.f + __expf(-sc));
        prow[q * 256] = p;
    }
}

// ---------------- K4: midpoint as GEMM: nom = P @ GV, den = P @ (gamma-1) -----
// grid (4 qtiles of 64, 16 bh, 8 n-eighths), 256 threads, 4x4 register blocking.
__global__ __launch_bounds__(256) void midgemm_kernel(const float* __restrict__ pp)
{
    __shared__ __align__(16) float Ps[16][64];   // [n-step][q]
    __shared__ __align__(16) float Gs[16][64];   // [n-step][d]
    __shared__ float gms[16];                    // gamma-1 per n-step

    int qt = blockIdx.x, bh = blockIdx.y, ns = blockIdx.z;
    int t = threadIdx.x, tx = t & 15, ty = t >> 4;
    int base = bh * 256, nb = ns * 32;
    int row0 = bh * 256 + qt * 64;               // global q-row base

    int lr = t >> 2, lk = (t & 3) * 4;
    const float* pptr = pp + (size_t)(row0 + lr) * 256 + nb + lk;

    ull acc[4][2];
    float dacc[4] = {0.f, 0.f, 0.f, 0.f};
#pragma unroll
    for (int i = 0; i < 4; i++) { acc[i][0] = 0ull; acc[i][1] = 0ull; }

#pragma unroll
    for (int k0 = 0; k0 < 32; k0 += 16) {
        float4 pv = *(const float4*)(pptr + k0);
        Ps[lk + 0][lr] = pv.x; Ps[lk + 1][lr] = pv.y;
        Ps[lk + 2][lr] = pv.z; Ps[lk + 3][lr] = pv.w;
        float4 gvv = *(const float4*)&g_gv[(size_t)(base + nb + k0 + ty) * 64 + tx * 4];
        *(float4*)&Gs[ty][tx * 4] = gvv;
        if (t < 16) gms[t] = g_gamma[base + nb + k0 + t] - 1.f;
        __syncthreads();
#pragma unroll
        for (int kk = 0; kk < 16; kk++) {
            float4 a = *(const float4*)&Ps[kk][ty * 4];
            ulonglong2 bb = *(const ulonglong2*)&Gs[kk][tx * 4];
            float gm = gms[kk];
            ull aii;
            PK2(aii, a.x, a.x);
            FMA2(acc[0][0], aii, bb.x, acc[0][0]); FMA2(acc[0][1], aii, bb.y, acc[0][1]);
            PK2(aii, a.y, a.y);
            FMA2(acc[1][0], aii, bb.x, acc[1][0]); FMA2(acc[1][1], aii, bb.y, acc[1][1]);
            PK2(aii, a.z, a.z);
            FMA2(acc[2][0], aii, bb.x, acc[2][0]); FMA2(acc[2][1], aii, bb.y, acc[2][1]);
            PK2(aii, a.w, a.w);
            FMA2(acc[3][0], aii, bb.x, acc[3][0]); FMA2(acc[3][1], aii, bb.y, acc[3][1]);
            dacc[0] = fmaf(a.x, gm, dacc[0]);
            dacc[1] = fmaf(a.y, gm, dacc[1]);
            dacc[2] = fmaf(a.z, gm, dacc[2]);
            dacc[3] = fmaf(a.w, gm, dacc[3]);
        }
        __syncthreads();
    }

#pragma unroll
    for (int i = 0; i < 4; i++) {
        float4 v;
        UPK2(v.x, v.y, acc[i][0]);
        UPK2(v.z, v.w, acc[i][1]);
        float* prow = &g_part[ns][(size_t)(row0 + ty * 4 + i) * 68];
        *(float4*)&prow[tx * 4] = v;
        if (tx == 0) prow[64] = dacc[i];
    }
}

// ---------------- K5: combine partials + scalar_mul/logmap0 fused + out -------
// logmap0(mobius_scalar_mul(0.5,y)) == 0.5*artanh(||y||) * y/||y|| exactly.
// grid (256 q, 2 b), 256 threads; warp w = head h, lane l = dims 2l,2l+1.
__global__ __launch_bounds__(256) void finalize_kernel(float* __restrict__ out)
{
    __shared__ float sh[8];
    int q = blockIdx.x, b = blockIdx.y;
    int t = threadIdx.x, w = t >> 5, l = t & 31;

    size_t row = (size_t)((b * 8 + w) * 256 + q) * 68;

    float a0 = 0.f, a1 = 0.f, dn = 0.f;
#pragma unroll
    for (int i = 0; i < 8; i++) {
        const float* r = &g_part[i][row];
        ull m = *(const ull*)&r[2 * l];
        float x0, x1; UPK2(x0, x1, m);
        a0 += x0; a1 += x1;
        dn += r[64];
    }

    float sg = (dn >= 0.f) ? 1.f : -1.f;
    float dd = sg * fmaxf(fabsf(dn), 1e-10f);
    float y0 = __fdividef(a0, dd);
    float y1 = __fdividef(a1, dd);

    float nn2 = warp_sum(y0 * y0 + y1 * y1);
    float nm = fmaxf(sqrtf(nn2), 1e-15f);
    float f = 0.5f * artanh_pos(nm) / nm;   // fused scalar_mul(0.5)+logmap0(HD)
    float u0 = f * y0, u1 = f * y1;

    float us = f * f * nn2;                 // ||u||^2 for this head
    if (l == 0) sh[w] = us;
    __syncthreads();
    float tot = 0.f;
#pragma unroll
    for (int i = 0; i < 8; i++) tot += sh[i];
    float tn = fmaxf(sqrtf(tot), 1e-15f);
    float fs = tanhf(tn) / tn;              // expmap0 over HID

    float* orow = out + (q * 2 + b) * 512 + w * 64;
    ull ov; PK2(ov, fs * u0, fs * u1);
    *(ull*)&orow[2 * l] = ov;
}

// ---------------- launch ------------------------------------------------------
extern "C" void kernel_launch(void* const* d_in, const int* in_sizes, int n_in,
                              void* d_out, int out_size)
{
    const float* qin = (const float*)d_in[0];
    const float* Wq  = (const float*)d_in[1];
    const float* bq  = (const float*)d_in[2];
    const float* Wk  = (const float*)d_in[3];
    const float* bk  = (const float*)d_in[4];
    const float* Wv  = (const float*)d_in[5];
    const float* bv  = (const float*)d_in[6];
    float* out = (float*)d_out;

    const int ctx_elems  = S_ * B_ * HID_;        // 262144
    const int prob_elems = B_ * NH_ * S_ * S_;    // 1048576

    float* pp;
    if (out_size >= ctx_elems + prob_elems) {
        pp = out + ctx_elems;
    } else {
        void* sym = nullptr;
        cudaGetSymbolAddress(&sym, g_probs);
        pp = (float*)sym;
    }

    prep_kernel<<<1, 32>>>();                      // slot 1 (diagnostic shim)
    gemm_kernel<<<dim3(12, 8, 4), 256>>>(qin, Wq, Wk, Wv);
    postproc_kernel<<<dim3(64, 3), 256>>>(qin, bq, bk, bv);
    scores_kernel<<<dim3(32, 16), 256>>>(pp);      // slot 4 -> gets profiled
    midgemm_kernel<<<dim3(4, 16, 8), 256>>>(pp);
    finalize_kernel<<<dim3(256, 2), 256>>>(out);
}

// round 16
// speedup vs baseline: 1.6241x; 1.6241x over previous
#include <cuda_runtime.h>
#include <math.h>

typedef unsigned long long ull;

// Problem constants
#define S_   256
#define B_   2
#define HID_ 512
#define NH_  8
#define HD_  64
#define NCH_ 2048

// ---------------- scratch ----------------------------------------------------
__device__ float g_mx  [4][3 * B_ * S_ * HID_];  // K-split partials (4)
__device__ float g_lin [2 * B_ * S_ * HID_];     // ql, kl only
__device__ float g_gv  [B_ * NCH_ * HD_];        // gamma * vl
__device__ float g_qn2 [B_ * NCH_];
__device__ float g_kl2 [B_ * NCH_];
__device__ float g_gamma[B_ * NCH_];
__device__ float g_probs[B_ * NH_ * S_ * S_];    // fallback if out has no room
__device__ float g_part[8][B_ * NH_ * S_ * 68];  // midpoint partials: 64 nom + den@64
__device__ float g_dummy[32];                    // prep_kernel sink

// ---------------- f32x2 packed helpers ---------------------------------------
#define FMA2(d, a, b, c) \
    asm("fma.rn.f32x2 %0, %1, %2, %3;" : "=l"(d) : "l"(a), "l"(b), "l"(c))
#define MUL2(d, a, b) \
    asm("mul.rn.f32x2 %0, %1, %2;" : "=l"(d) : "l"(a), "l"(b))
#define ADD2(d, a, b) \
    asm("add.rn.f32x2 %0, %1, %2;" : "=l"(d) : "l"(a), "l"(b))
#define PK2(d, lo, hi) \
    asm("mov.b64 %0, {%1, %2};" : "=l"(d) : "f"(lo), "f"(hi))
#define UPK2(lo, hi, s) \
    asm("mov.b64 {%0, %1}, %2;" : "=f"(lo), "=f"(hi) : "l"(s))

__device__ __forceinline__ float frcp(float x) {
    float r; asm("rcp.approx.f32 %0, %1;" : "=f"(r) : "f"(x)); return r;
}

__device__ __forceinline__ float artanh_pos(float x) {
    x = fminf(x, 1.f - 1e-7f);
    return 0.5f * __logf((1.f + x) / (1.f - x));
}

__device__ __forceinline__ float warp_sum(float v) {
#pragma unroll
    for (int o = 16; o; o >>= 1) v += __shfl_xor_sync(0xffffffffu, v, o);
    return v;
}

__device__ __forceinline__ float dot4(float4 a, float4 b) {
    return a.x * b.x + a.y * b.y + a.z * b.z + a.w * b.w;
}

// ---------------- K0: trivial prep (keeps scores in profiled slot 4) ----------
__global__ void prep_kernel()
{
    if (threadIdx.x < 32) g_dummy[threadIdx.x] = (float)threadIdx.x;
}

// ---------------- K1: MX = X @ W^T -------------------------------------------
// 64x128 tile, 4q x 8i register blocking, K-split 4, register prefetch.
__global__ __launch_bounds__(256) void gemm_kernel(
    const float* __restrict__ qin, const float* __restrict__ Wq,
    const float* __restrict__ Wk,  const float* __restrict__ Wv)
{
    __shared__ __align__(16) float Xs[16][64];
    __shared__ __align__(16) float Ws[16][128];

    int bx = blockIdx.x, by = blockIdx.y, ks = blockIdx.z;
    int t  = threadIdx.x;
    int tx = t & 15, ty = t >> 4;

    int m = bx >> 2;
    const float* W = (m == 0) ? Wq : (m == 1) ? Wk : Wv;
    int ibase = (bx & 3) * 128;

    int lr = t >> 2;           // 0..63 (X row)
    int lk = (t & 3) * 4;      // 0,4,8,12
    int wr = t >> 1;           // 0..127 (W row / out col)
    int wk = (t & 1) * 8;      // 0,8

    int grow = by * 64 + lr;
    int gb = grow >> 8, gs = grow & 255;
    const float* xptr = qin + (gs * 2 + gb) * 512 + lk;
    const float* wptr = W + (ibase + wr) * 512 + wk;

    ull acc[4][4];
#pragma unroll
    for (int i = 0; i < 4; i++)
#pragma unroll
        for (int j = 0; j < 4; j++) acc[i][j] = 0ull;

    int k0beg = ks * 128, k0end = k0beg + 128;
    float4 xv  = *(const float4*)(xptr + k0beg);
    float4 wv0 = *(const float4*)(wptr + k0beg);
    float4 wv1 = *(const float4*)(wptr + k0beg + 4);

    for (int k0 = k0beg; k0 < k0end; k0 += 16) {
        Xs[lk + 0][lr] = xv.x; Xs[lk + 1][lr] = xv.y;
        Xs[lk + 2][lr] = xv.z; Xs[lk + 3][lr] = xv.w;
        Ws[wk + 0][wr] = wv0.x; Ws[wk + 1][wr] = wv0.y;
        Ws[wk + 2][wr] = wv0.z; Ws[wk + 3][wr] = wv0.w;
        Ws[wk + 4][wr] = wv1.x; Ws[wk + 5][wr] = wv1.y;
        Ws[wk + 6][wr] = wv1.z; Ws[wk + 7][wr] = wv1.w;
        __syncthreads();
        if (k0 + 16 < k0end) {               // register prefetch of next stage
            xv  = *(const float4*)(xptr + k0 + 16);
            wv0 = *(const float4*)(wptr + k0 + 16);
            wv1 = *(const float4*)(wptr + k0 + 20);
        }
#pragma unroll
        for (int kk = 0; kk < 16; kk++) {
            float4 a = *(const float4*)&Xs[kk][ty * 4];
            ulonglong2 b0 = *(const ulonglong2*)&Ws[kk][tx * 4];
            ulonglong2 b1 = *(const ulonglong2*)&Ws[kk][64 + tx * 4];
            ull aii;
            PK2(aii, a.x, a.x);
            FMA2(acc[0][0], aii, b0.x, acc[0][0]); FMA2(acc[0][1], aii, b0.y, acc[0][1]);
            FMA2(acc[0][2], aii, b1.x, acc[0][2]); FMA2(acc[0][3], aii, b1.y, acc[0][3]);
            PK2(aii, a.y, a.y);
            FMA2(acc[1][0], aii, b0.x, acc[1][0]); FMA2(acc[1][1], aii, b0.y, acc[1][1]);
            FMA2(acc[1][2], aii, b1.x, acc[1][2]); FMA2(acc[1][3], aii, b1.y, acc[1][3]);
            PK2(aii, a.z, a.z);
            FMA2(acc[2][0], aii, b0.x, acc[2][0]); FMA2(acc[2][1], aii, b0.y, acc[2][1]);
            FMA2(acc[2][2], aii, b1.x, acc[2][2]); FMA2(acc[2][3], aii, b1.y, acc[2][3]);
            PK2(aii, a.w, a.w);
            FMA2(acc[3][0], aii, b0.x, acc[3][0]); FMA2(acc[3][1], aii, b0.y, acc[3][1]);
            FMA2(acc[3][2], aii, b1.x, acc[3][2]); FMA2(acc[3][3], aii, b1.y, acc[3][3]);
        }
        __syncthreads();
    }

    int row0 = by * 64 + ty * 4;
#pragma unroll
    for (int i = 0; i < 4; i++) {
        int row = row0 + i;
        int b = row >> 8, s = row & 255;
        float* orow = &g_mx[ks][(((m * 2 + b) * 256 + s) * 512)];
        float4 v0, v1;
        UPK2(v0.x, v0.y, acc[i][0]); UPK2(v0.z, v0.w, acc[i][1]);
        UPK2(v1.x, v1.y, acc[i][2]); UPK2(v1.z, v1.w, acc[i][3]);
        *(float4*)&orow[ibase + tx * 4]      = v0;
        *(float4*)&orow[ibase + 64 + tx * 4] = v1;
    }
}

// ---------------- K2: manifold linear + logmap0 + chunk expmap0 ---------------
__global__ __launch_bounds__(256) void postproc_kernel(
    const float* __restrict__ qin, const float* __restrict__ bq,
    const float* __restrict__ bk,  const float* __restrict__ bv)
{
    int t = threadIdx.x, w = t >> 5, l = t & 31;
    int r = blockIdx.x * 8 + w;         // 0..511
    int m = blockIdx.y;
    int b = r >> 8, s = r & 255;

    const float* xrow = qin + (s * 2 + b) * 512;
    size_t mxoff = (size_t)((m * 2 + b) * 256 + s) * 512;
    const float* bias = (m == 0) ? bq : (m == 1) ? bk : bv;

    float4 xv[4], mv[4], bb[4];
#pragma unroll
    for (int j = 0; j < 4; j++) {
        int e = l * 4 + 128 * j;
        xv[j] = *(const float4*)(xrow + e);
        float4 p0 = *(const float4*)&g_mx[0][mxoff + e];
        float4 p1 = *(const float4*)&g_mx[1][mxoff + e];
        float4 p2 = *(const float4*)&g_mx[2][mxoff + e];
        float4 p3 = *(const float4*)&g_mx[3][mxoff + e];
        mv[j] = make_float4((p0.x + p1.x) + (p2.x + p3.x),
                            (p0.y + p1.y) + (p2.y + p3.y),
                            (p0.z + p1.z) + (p2.z + p3.z),
                            (p0.w + p1.w) + (p2.w + p3.w));
        bb[j] = *(const float4*)(bias + e);
    }

    float sx = 0.f, smx = 0.f;
#pragma unroll
    for (int j = 0; j < 4; j++) { sx += dot4(xv[j], xv[j]); smx += dot4(mv[j], mv[j]); }
    sx = warp_sum(sx); smx = warp_sum(smx);

    float xn  = fmaxf(sqrtf(sx),  1e-15f);
    float mxn = fmaxf(sqrtf(smx), 1e-15f);
    float scm = tanhf((mxn / xn) * artanh_pos(xn)) / mxn;

    float xy = 0.f, x2 = 0.f, y2 = 0.f;
    float4 rv[4];
#pragma unroll
    for (int j = 0; j < 4; j++) {
        rv[j] = make_float4(scm * mv[j].x, scm * mv[j].y, scm * mv[j].z, scm * mv[j].w);
        xy += dot4(rv[j], bb[j]); x2 += dot4(rv[j], rv[j]); y2 += dot4(bb[j], bb[j]);
    }
    xy = warp_sum(xy); x2 = warp_sum(x2); y2 = warp_sum(y2);

    float ca = 1.f + 2.f * xy + y2;
    float cb = 1.f - x2;
    float den = fmaxf(1.f + 2.f * xy + x2 * y2, 1e-15f);
    float rd = __fdividef(1.f, den);

    float so = 0.f;
    float4 ov[4];
#pragma unroll
    for (int j = 0; j < 4; j++) {
        ov[j] = make_float4((ca * rv[j].x + cb * bb[j].x) * rd,
                            (ca * rv[j].y + cb * bb[j].y) * rd,
                            (ca * rv[j].z + cb * bb[j].z) * rd,
                            (ca * rv[j].w + cb * bb[j].w) * rd);
        so += dot4(ov[j], ov[j]);
    }
    so = warp_sum(so);
    float n = fmaxf(sqrtf(so), 1e-15f);
    float pf = (n > 0.996f) ? (0.996f / n) : 1.f;   // projx
    n = fminf(n, 0.996f);
    float ls = artanh_pos(n) / n * pf;              // logmap0 over HID (+proj)

    float* Lrow = g_lin + ((m * 2 + b) * 256 + s) * 512;
#pragma unroll
    for (int j = 0; j < 4; j++) {
        float4 uv = make_float4(ls * ov[j].x, ls * ov[j].y, ls * ov[j].z, ls * ov[j].w);
        float cu = dot4(uv, uv);
        cu += __shfl_xor_sync(0xffffffffu, cu, 1);
        cu += __shfl_xor_sync(0xffffffffu, cu, 2);
        cu += __shfl_xor_sync(0xffffffffu, cu, 4);
        cu += __shfl_xor_sync(0xffffffffu, cu, 8);   // sum over 16-lane group
        float cn = fmaxf(sqrtf(cu), 1e-15f);
        float es = tanhf(cn) / cn;                   // chunk expmap0
        float4 lv = make_float4(es * uv.x, es * uv.y, es * uv.z, es * uv.w);
        int c = (l >> 4) + 2 * j;                    // chunk within row
        int idx = b * NCH_ + s * 8 + c;              // flat (b, h*256+s2)
        if (m < 2) {
            *(float4*)(Lrow + l * 4 + 128 * j) = lv;
            if ((l & 15) == 0) {
                float st = es * es * cu;
                if (m == 0) g_qn2[idx] = st;
                else        g_kl2[idx] = st;
            }
        } else {
            float st = es * es * cu;                 // group-uniform
            float ga = 2.f / fmaxf(1.f - st, 1e-15f);
            *(float4*)&g_gv[(size_t)idx * 64 + (l & 15) * 4] =
                make_float4(ga * lv.x, ga * lv.y, ga * lv.z, ga * lv.w);
            if ((l & 15) == 0) g_gamma[idx] = ga;
        }
    }
}

// ---------------- K3: pairwise scores + sigmoid (lane-pair n-split) ----------
// grid (32 qtiles of 8, 16 bh, 2 n-halves), 256 threads.
// Lanes l and l^16 co-own one n; each holds HALF the K-row in registers
// (kr2[16] = 32 regs) and computes 32-dim partials; shfl_xor(16) merges.
__global__ __launch_bounds__(256) void scores_kernel(float* __restrict__ pp)
{
    __shared__ __align__(16) float qs[8 * 64];
    __shared__ float q2s[8];

    int qt = blockIdx.x, bh = blockIdx.y, ns = blockIdx.z;
    int base = bh * 256;
    int qg0 = qt * 8;
    int t = threadIdx.x;
    int w = t >> 5, l = t & 31;
    int nh = l >> 4;                  // half index (which 32 dims)
    int nl = l & 15;
    int n = ns * 128 + w * 16 + nl;   // this pair's n

    const float* gql = g_lin;
    const float* gkl = g_lin + B_ * S_ * HID_;

    for (int idx = t; idx < 8 * 64; idx += 256)
        qs[idx] = gql[(base + qg0) * 64 + idx];
    if (t < 8) q2s[t] = g_qn2[base + qg0 + t];

    // half K-row: dims [nh*32, nh*32+32)
    ull kr2[16];
    {
        const float* krow = gkl + (size_t)(base + n) * 64 + nh * 32;
#pragma unroll
        for (int i = 0; i < 8; i++) {
            ulonglong2 v = *(const ulonglong2*)(krow + i * 4);
            kr2[2 * i]     = v.x;
            kr2[2 * i + 1] = v.y;
        }
    }
    float y2 = g_kl2[base + n];
    __syncthreads();

    float* prow = pp + (size_t)(bh * 256 + qg0) * 256 + n;

    for (int q = 0; q < 8; q++) {
        const ulonglong2* qr2 = (const ulonglong2*)&qs[q * 64 + nh * 32];
        float x2 = q2s[q];

        // partial dot over this half (16 f32x2)
        ull a0 = 0ull, a1 = 0ull, a2 = 0ull, a3 = 0ull;
#pragma unroll
        for (int i = 0; i < 8; i += 2) {
            ulonglong2 qa = qr2[i];
            ulonglong2 qb = qr2[i + 1];
            FMA2(a0, kr2[2 * i],     qa.x, a0);
            FMA2(a1, kr2[2 * i + 1], qa.y, a1);
            FMA2(a2, kr2[2 * i + 2], qb.x, a2);
            FMA2(a3, kr2[2 * i + 3], qb.y, a3);
        }
        float s0, s1, s2, s3, s4, s5, s6, s7;
        UPK2(s0, s1, a0); UPK2(s2, s3, a1); UPK2(s4, s5, a2); UPK2(s6, s7, a3);
        float xyp = ((s0 + s1) + (s2 + s3)) + ((s4 + s5) + (s6 + s7));
        float xy = xyp + __shfl_xor_sync(0xffffffffu, xyp, 16);  // merge halves

        float A  = 1.f - 2.f * xy + y2;
        float Bc = 1.f - x2;
        float den = fmaxf(1.f - 2.f * xy + x2 * y2, 1e-15f);
        float r = __fdividef(A, Bc);
        float fsc = __fdividef(den, Bc);
        fsc *= fsc;                                  // (den/Bc)^2

        ull nr2;
        PK2(nr2, -r, -r);

        // partial sum 1/(k - r*q)^2 over this half; 4-way rcp combine
        float t0 = 0.f;
#pragma unroll
        for (int i = 0; i < 8; i++) {
            ulonglong2 qv = qr2[i];
            ull num, sqa, sqb, sv, pv;
            FMA2(num, nr2, qv.x, kr2[2 * i]);
            MUL2(sqa, num, num);
            FMA2(num, nr2, qv.y, kr2[2 * i + 1]);
            MUL2(sqb, num, num);
            ADD2(sv, sqa, sqb);
            MUL2(pv, sqa, sqb);
            float svl, svh, pvl, pvh;
            UPK2(svl, svh, sv);
            UPK2(pvl, pvh, pv);
            float num4 = fmaf(svl, pvh, svh * pvl);
            float den4 = fmaxf(pvl * pvh, 1e-37f);
            t0 = fmaf(num4, frcp(den4), t0);
        }
        float t0t = t0 + __shfl_xor_sync(0xffffffffu, t0, 16);   // merge halves

        float tacc = t0t * fsc;
        float tt = rsqrtf(tacc);
        float sc = -2.f * artanh_pos(tt);
        sc = fminf(fmaxf(sc, -1e10f), 1e10f);
        float p = __fdividef(1.f, 1.f + __expf(-sc));
        if (nh == 0) prow[q * 256] = p;
    }
}

// ---------------- K4: midpoint as GEMM: nom = P @ GV, den = P @ (gamma-1) -----
// grid (4 qtiles of 64, 16 bh, 8 n-eighths), 256 threads, 4x4 register blocking.
__global__ __launch_bounds__(256) void midgemm_kernel(const float* __restrict__ pp)
{
    __shared__ __align__(16) float Ps[16][64];   // [n-step][q]
    __shared__ __align__(16) float Gs[16][64];   // [n-step][d]
    __shared__ float gms[16];                    // gamma-1 per n-step

    int qt = blockIdx.x, bh = blockIdx.y, ns = blockIdx.z;
    int t = threadIdx.x, tx = t & 15, ty = t >> 4;
    int base = bh * 256, nb = ns * 32;
    int row0 = bh * 256 + qt * 64;               // global q-row base

    int lr = t >> 2, lk = (t & 3) * 4;
    const float* pptr = pp + (size_t)(row0 + lr) * 256 + nb + lk;

    ull acc[4][2];
    float dacc[4] = {0.f, 0.f, 0.f, 0.f};
#pragma unroll
    for (int i = 0; i < 4; i++) { acc[i][0] = 0ull; acc[i][1] = 0ull; }

#pragma unroll
    for (int k0 = 0; k0 < 32; k0 += 16) {
        float4 pv = *(const float4*)(pptr + k0);
        Ps[lk + 0][lr] = pv.x; Ps[lk + 1][lr] = pv.y;
        Ps[lk + 2][lr] = pv.z; Ps[lk + 3][lr] = pv.w;
        float4 gvv = *(const float4*)&g_gv[(size_t)(base + nb + k0 + ty) * 64 + tx * 4];
        *(float4*)&Gs[ty][tx * 4] = gvv;
        if (t < 16) gms[t] = g_gamma[base + nb + k0 + t] - 1.f;
        __syncthreads();
#pragma unroll
        for (int kk = 0; kk < 16; kk++) {
            float4 a = *(const float4*)&Ps[kk][ty * 4];
            ulonglong2 bb = *(const ulonglong2*)&Gs[kk][tx * 4];
            float gm = gms[kk];
            ull aii;
            PK2(aii, a.x, a.x);
            FMA2(acc[0][0], aii, bb.x, acc[0][0]); FMA2(acc[0][1], aii, bb.y, acc[0][1]);
            PK2(aii, a.y, a.y);
            FMA2(acc[1][0], aii, bb.x, acc[1][0]); FMA2(acc[1][1], aii, bb.y, acc[1][1]);
            PK2(aii, a.z, a.z);
            FMA2(acc[2][0], aii, bb.x, acc[2][0]); FMA2(acc[2][1], aii, bb.y, acc[2][1]);
            PK2(aii, a.w, a.w);
            FMA2(acc[3][0], aii, bb.x, acc[3][0]); FMA2(acc[3][1], aii, bb.y, acc[3][1]);
            dacc[0] = fmaf(a.x, gm, dacc[0]);
            dacc[1] = fmaf(a.y, gm, dacc[1]);
            dacc[2] = fmaf(a.z, gm, dacc[2]);
            dacc[3] = fmaf(a.w, gm, dacc[3]);
        }
        __syncthreads();
    }

#pragma unroll
    for (int i = 0; i < 4; i++) {
        float4 v;
        UPK2(v.x, v.y, acc[i][0]);
        UPK2(v.z, v.w, acc[i][1]);
        float* prow = &g_part[ns][(size_t)(row0 + ty * 4 + i) * 68];
        *(float4*)&prow[tx * 4] = v;
        if (tx == 0) prow[64] = dacc[i];
    }
}

// ---------------- K5: combine partials + scalar_mul/logmap0 fused + out -------
__global__ __launch_bounds__(256) void finalize_kernel(float* __restrict__ out)
{
    __shared__ float sh[8];
    int q = blockIdx.x, b = blockIdx.y;
    int t = threadIdx.x, w = t >> 5, l = t & 31;

    size_t row = (size_t)((b * 8 + w) * 256 + q) * 68;

    float a0 = 0.f, a1 = 0.f, dn = 0.f;
#pragma unroll
    for (int i = 0; i < 8; i++) {
        const float* r = &g_part[i][row];
        ull m = *(const ull*)&r[2 * l];
        float x0, x1; UPK2(x0, x1, m);
        a0 += x0; a1 += x1;
        dn += r[64];
    }

    float sg = (dn >= 0.f) ? 1.f : -1.f;
    float dd = sg * fmaxf(fabsf(dn), 1e-10f);
    float y0 = __fdividef(a0, dd);
    float y1 = __fdividef(a1, dd);

    float nn2 = warp_sum(y0 * y0 + y1 * y1);
    float nm = fmaxf(sqrtf(nn2), 1e-15f);
    float f = 0.5f * artanh_pos(nm) / nm;   // fused scalar_mul(0.5)+logmap0(HD)
    float u0 = f * y0, u1 = f * y1;

    float us = f * f * nn2;                 // ||u||^2 for this head
    if (l == 0) sh[w] = us;
    __syncthreads();
    float tot = 0.f;
#pragma unroll
    for (int i = 0; i < 8; i++) tot += sh[i];
    float tn = fmaxf(sqrtf(tot), 1e-15f);
    float fs = tanhf(tn) / tn;              // expmap0 over HID

    float* orow = out + (q * 2 + b) * 512 + w * 64;
    ull ov; PK2(ov, fs * u0, fs * u1);
    *(ull*)&orow[2 * l] = ov;
}

// ---------------- launch ------------------------------------------------------
extern "C" void kernel_launch(void* const* d_in, const int* in_sizes, int n_in,
                              void* d_out, int out_size)
{
    const float* qin = (const float*)d_in[0];
    const float* Wq  = (const float*)d_in[1];
    const float* bq  = (const float*)d_in[2];
    const float* Wk  = (const float*)d_in[3];
    const float* bk  = (const float*)d_in[4];
    const float* Wv  = (const float*)d_in[5];
    const float* bv  = (const float*)d_in[6];
    float* out = (float*)d_out;

    const int ctx_elems  = S_ * B_ * HID_;        // 262144
    const int prob_elems = B_ * NH_ * S_ * S_;    // 1048576

    float* pp;
    if (out_size >= ctx_elems + prob_elems) {
        pp = out + ctx_elems;
    } else {
        void* sym = nullptr;
        cudaGetSymbolAddress(&sym, g_probs);
        pp = (float*)sym;
    }

    prep_kernel<<<1, 32>>>();                      // slot 1 (diagnostic shim)
    gemm_kernel<<<dim3(12, 8, 4), 256>>>(qin, Wq, Wk, Wv);
    postproc_kernel<<<dim3(64, 3), 256>>>(qin, bq, bk, bv);
    scores_kernel<<<dim3(32, 16, 2), 256>>>(pp);   // slot 4 -> gets profiled
    midgemm_kernel<<<dim3(4, 16, 8), 256>>>(pp);
    finalize_kernel<<<dim3(256, 2), 256>>>(out);
}

// round 17
// speedup vs baseline: 1.7101x; 1.0529x over previous
#include <cuda_runtime.h>
#include <math.h>

typedef unsigned long long ull;

// Problem constants
#define S_   256
#define B_   2
#define HID_ 512
#define NH_  8
#define HD_  64
#define NCH_ 2048

// ---------------- scratch ----------------------------------------------------
__device__ float g_mx  [4][3 * B_ * S_ * HID_];  // K-split partials (4)
__device__ float g_lin [2 * B_ * S_ * HID_];     // ql, kl only
__device__ float g_gv  [B_ * NCH_ * HD_];        // gamma * vl
__device__ float g_qn2 [B_ * NCH_];
__device__ float g_kl2 [B_ * NCH_];
__device__ float g_gamma[B_ * NCH_];
__device__ float g_probs[B_ * NH_ * S_ * S_];    // fallback if out has no room
__device__ float g_part[8][B_ * NH_ * S_ * 68];  // midpoint partials: 64 nom + den@64

// ---------------- f32x2 packed helpers ---------------------------------------
#define FMA2(d, a, b, c) \
    asm("fma.rn.f32x2 %0, %1, %2, %3;" : "=l"(d) : "l"(a), "l"(b), "l"(c))
#define MUL2(d, a, b) \
    asm("mul.rn.f32x2 %0, %1, %2;" : "=l"(d) : "l"(a), "l"(b))
#define ADD2(d, a, b) \
    asm("add.rn.f32x2 %0, %1, %2;" : "=l"(d) : "l"(a), "l"(b))
#define PK2(d, lo, hi) \
    asm("mov.b64 %0, {%1, %2};" : "=l"(d) : "f"(lo), "f"(hi))
#define UPK2(lo, hi, s) \
    asm("mov.b64 {%0, %1}, %2;" : "=f"(lo), "=f"(hi) : "l"(s))

__device__ __forceinline__ float frcp(float x) {
    float r; asm("rcp.approx.f32 %0, %1;" : "=f"(r) : "f"(x)); return r;
}

__device__ __forceinline__ float artanh_pos(float x) {
    x = fminf(x, 1.f - 1e-7f);
    return 0.5f * __logf((1.f + x) / (1.f - x));
}

__device__ __forceinline__ float warp_sum(float v) {
#pragma unroll
    for (int o = 16; o; o >>= 1) v += __shfl_xor_sync(0xffffffffu, v, o);
    return v;
}

__device__ __forceinline__ float dot4(float4 a, float4 b) {
    return a.x * b.x + a.y * b.y + a.z * b.z + a.w * b.w;
}

// ---------------- K1: MX = X @ W^T -------------------------------------------
// 64x128 tile, 4q x 8i register blocking, K-split 4, register prefetch.
__global__ __launch_bounds__(256) void gemm_kernel(
    const float* __restrict__ qin, const float* __restrict__ Wq,
    const float* __restrict__ Wk,  const float* __restrict__ Wv)
{
    __shared__ __align__(16) float Xs[16][64];
    __shared__ __align__(16) float Ws[16][128];

    int bx = blockIdx.x, by = blockIdx.y, ks = blockIdx.z;
    int t  = threadIdx.x;
    int tx = t & 15, ty = t >> 4;

    int m = bx >> 2;
    const float* W = (m == 0) ? Wq : (m == 1) ? Wk : Wv;
    int ibase = (bx & 3) * 128;

    int lr = t >> 2;           // 0..63 (X row)
    int lk = (t & 3) * 4;      // 0,4,8,12
    int wr = t >> 1;           // 0..127 (W row / out col)
    int wk = (t & 1) * 8;      // 0,8

    int grow = by * 64 + lr;
    int gb = grow >> 8, gs = grow & 255;
    const float* xptr = qin + (gs * 2 + gb) * 512 + lk;
    const float* wptr = W + (ibase + wr) * 512 + wk;

    ull acc[4][4];
#pragma unroll
    for (int i = 0; i < 4; i++)
#pragma unroll
        for (int j = 0; j < 4; j++) acc[i][j] = 0ull;

    int k0beg = ks * 128, k0end = k0beg + 128;
    float4 xv  = *(const float4*)(xptr + k0beg);
    float4 wv0 = *(const float4*)(wptr + k0beg);
    float4 wv1 = *(const float4*)(wptr + k0beg + 4);

    for (int k0 = k0beg; k0 < k0end; k0 += 16) {
        Xs[lk + 0][lr] = xv.x; Xs[lk + 1][lr] = xv.y;
        Xs[lk + 2][lr] = xv.z; Xs[lk + 3][lr] = xv.w;
        Ws[wk + 0][wr] = wv0.x; Ws[wk + 1][wr] = wv0.y;
        Ws[wk + 2][wr] = wv0.z; Ws[wk + 3][wr] = wv0.w;
        Ws[wk + 4][wr] = wv1.x; Ws[wk + 5][wr] = wv1.y;
        Ws[wk + 6][wr] = wv1.z; Ws[wk + 7][wr] = wv1.w;
        __syncthreads();
        if (k0 + 16 < k0end) {               // register prefetch of next stage
            xv  = *(const float4*)(xptr + k0 + 16);
            wv0 = *(const float4*)(wptr + k0 + 16);
            wv1 = *(const float4*)(wptr + k0 + 20);
        }
#pragma unroll
        for (int kk = 0; kk < 16; kk++) {
            float4 a = *(const float4*)&Xs[kk][ty * 4];
            ulonglong2 b0 = *(const ulonglong2*)&Ws[kk][tx * 4];
            ulonglong2 b1 = *(const ulonglong2*)&Ws[kk][64 + tx * 4];
            ull aii;
            PK2(aii, a.x, a.x);
            FMA2(acc[0][0], aii, b0.x, acc[0][0]); FMA2(acc[0][1], aii, b0.y, acc[0][1]);
            FMA2(acc[0][2], aii, b1.x, acc[0][2]); FMA2(acc[0][3], aii, b1.y, acc[0][3]);
            PK2(aii, a.y, a.y);
            FMA2(acc[1][0], aii, b0.x, acc[1][0]); FMA2(acc[1][1], aii, b0.y, acc[1][1]);
            FMA2(acc[1][2], aii, b1.x, acc[1][2]); FMA2(acc[1][3], aii, b1.y, acc[1][3]);
            PK2(aii, a.z, a.z);
            FMA2(acc[2][0], aii, b0.x, acc[2][0]); FMA2(acc[2][1], aii, b0.y, acc[2][1]);
            FMA2(acc[2][2], aii, b1.x, acc[2][2]); FMA2(acc[2][3], aii, b1.y, acc[2][3]);
            PK2(aii, a.w, a.w);
            FMA2(acc[3][0], aii, b0.x, acc[3][0]); FMA2(acc[3][1], aii, b0.y, acc[3][1]);
            FMA2(acc[3][2], aii, b1.x, acc[3][2]); FMA2(acc[3][3], aii, b1.y, acc[3][3]);
        }
        __syncthreads();
    }

    int row0 = by * 64 + ty * 4;
#pragma unroll
    for (int i = 0; i < 4; i++) {
        int row = row0 + i;
        int b = row >> 8, s = row & 255;
        float* orow = &g_mx[ks][(((m * 2 + b) * 256 + s) * 512)];
        float4 v0, v1;
        UPK2(v0.x, v0.y, acc[i][0]); UPK2(v0.z, v0.w, acc[i][1]);
        UPK2(v1.x, v1.y, acc[i][2]); UPK2(v1.z, v1.w, acc[i][3]);
        *(float4*)&orow[ibase + tx * 4]      = v0;
        *(float4*)&orow[ibase + 64 + tx * 4] = v1;
    }
}

// ---------------- K2: manifold linear + logmap0 + chunk expmap0 ---------------
__global__ __launch_bounds__(256) void postproc_kernel(
    const float* __restrict__ qin, const float* __restrict__ bq,
    const float* __restrict__ bk,  const float* __restrict__ bv)
{
    int t = threadIdx.x, w = t >> 5, l = t & 31;
    int r = blockIdx.x * 8 + w;         // 0..511
    int m = blockIdx.y;
    int b = r >> 8, s = r & 255;

    const float* xrow = qin + (s * 2 + b) * 512;
    size_t mxoff = (size_t)((m * 2 + b) * 256 + s) * 512;
    const float* bias = (m == 0) ? bq : (m == 1) ? bk : bv;

    float4 xv[4], mv[4], bb[4];
#pragma unroll
    for (int j = 0; j < 4; j++) {
        int e = l * 4 + 128 * j;
        xv[j] = *(const float4*)(xrow + e);
        float4 p0 = *(const float4*)&g_mx[0][mxoff + e];
        float4 p1 = *(const float4*)&g_mx[1][mxoff + e];
        float4 p2 = *(const float4*)&g_mx[2][mxoff + e];
        float4 p3 = *(const float4*)&g_mx[3][mxoff + e];
        mv[j] = make_float4((p0.x + p1.x) + (p2.x + p3.x),
                            (p0.y + p1.y) + (p2.y + p3.y),
                            (p0.z + p1.z) + (p2.z + p3.z),
                            (p0.w + p1.w) + (p2.w + p3.w));
        bb[j] = *(const float4*)(bias + e);
    }

    float sx = 0.f, smx = 0.f;
#pragma unroll
    for (int j = 0; j < 4; j++) { sx += dot4(xv[j], xv[j]); smx += dot4(mv[j], mv[j]); }
    sx = warp_sum(sx); smx = warp_sum(smx);

    float xn  = fmaxf(sqrtf(sx),  1e-15f);
    float mxn = fmaxf(sqrtf(smx), 1e-15f);
    float scm = tanhf((mxn / xn) * artanh_pos(xn)) / mxn;

    float xy = 0.f, x2 = 0.f, y2 = 0.f;
    float4 rv[4];
#pragma unroll
    for (int j = 0; j < 4; j++) {
        rv[j] = make_float4(scm * mv[j].x, scm * mv[j].y, scm * mv[j].z, scm * mv[j].w);
        xy += dot4(rv[j], bb[j]); x2 += dot4(rv[j], rv[j]); y2 += dot4(bb[j], bb[j]);
    }
    xy = warp_sum(xy); x2 = warp_sum(x2); y2 = warp_sum(y2);

    float ca = 1.f + 2.f * xy + y2;
    float cb = 1.f - x2;
    float den = fmaxf(1.f + 2.f * xy + x2 * y2, 1e-15f);
    float rd = __fdividef(1.f, den);

    float so = 0.f;
    float4 ov[4];
#pragma unroll
    for (int j = 0; j < 4; j++) {
        ov[j] = make_float4((ca * rv[j].x + cb * bb[j].x) * rd,
                            (ca * rv[j].y + cb * bb[j].y) * rd,
                            (ca * rv[j].z + cb * bb[j].z) * rd,
                            (ca * rv[j].w + cb * bb[j].w) * rd);
        so += dot4(ov[j], ov[j]);
    }
    so = warp_sum(so);
    float n = fmaxf(sqrtf(so), 1e-15f);
    float pf = (n > 0.996f) ? (0.996f / n) : 1.f;   // projx
    n = fminf(n, 0.996f);
    float ls = artanh_pos(n) / n * pf;              // logmap0 over HID (+proj)

    float* Lrow = g_lin + ((m * 2 + b) * 256 + s) * 512;
#pragma unroll
    for (int j = 0; j < 4; j++) {
        float4 uv = make_float4(ls * ov[j].x, ls * ov[j].y, ls * ov[j].z, ls * ov[j].w);
        float cu = dot4(uv, uv);
        cu += __shfl_xor_sync(0xffffffffu, cu, 1);
        cu += __shfl_xor_sync(0xffffffffu, cu, 2);
        cu += __shfl_xor_sync(0xffffffffu, cu, 4);
        cu += __shfl_xor_sync(0xffffffffu, cu, 8);   // sum over 16-lane group
        float cn = fmaxf(sqrtf(cu), 1e-15f);
        float es = tanhf(cn) / cn;                   // chunk expmap0
        float4 lv = make_float4(es * uv.x, es * uv.y, es * uv.z, es * uv.w);
        int c = (l >> 4) + 2 * j;                    // chunk within row
        int idx = b * NCH_ + s * 8 + c;              // flat (b, h*256+s2)
        if (m < 2) {
            *(float4*)(Lrow + l * 4 + 128 * j) = lv;
            if ((l & 15) == 0) {
                float st = es * es * cu;
                if (m == 0) g_qn2[idx] = st;
                else        g_kl2[idx] = st;
            }
        } else {
            float st = es * es * cu;                 // group-uniform
            float ga = 2.f / fmaxf(1.f - st, 1e-15f);
            *(float4*)&g_gv[(size_t)idx * 64 + (l & 15) * 4] =
                make_float4(ga * lv.x, ga * lv.y, ga * lv.z, ga * lv.w);
            if ((l & 15) == 0) g_gamma[idx] = ga;
        }
    }
}

// ---------------- K3: pairwise scores + sigmoid (lane-pair n-split) ----------
// grid (32 qtiles of 8, 16 bh, 2 n-halves), 256 threads.
// Lanes l and l^16 co-own one n; each holds HALF the K-row in registers.
// Tail identity: sigmoid(-2*artanh(clip(t1))) == (1 - min(t1, 1-1e-7)) / 2.
__global__ __launch_bounds__(256) void scores_kernel(float* __restrict__ pp)
{
    __shared__ __align__(16) float qs[8 * 64];
    __shared__ float q2s[8];

    int qt = blockIdx.x, bh = blockIdx.y, ns = blockIdx.z;
    int base = bh * 256;
    int qg0 = qt * 8;
    int t = threadIdx.x;
    int w = t >> 5, l = t & 31;
    int nh = l >> 4;                  // half index (which 32 dims)
    int nl = l & 15;
    int n = ns * 128 + w * 16 + nl;   // this pair's n

    const float* gql = g_lin;
    const float* gkl = g_lin + B_ * S_ * HID_;

    for (int idx = t; idx < 8 * 64; idx += 256)
        qs[idx] = gql[(base + qg0) * 64 + idx];
    if (t < 8) q2s[t] = g_qn2[base + qg0 + t];

    // half K-row: dims [nh*32, nh*32+32)
    ull kr2[16];
    {
        const float* krow = gkl + (size_t)(base + n) * 64 + nh * 32;
#pragma unroll
        for (int i = 0; i < 8; i++) {
            ulonglong2 v = *(const ulonglong2*)(krow + i * 4);
            kr2[2 * i]     = v.x;
            kr2[2 * i + 1] = v.y;
        }
    }
    float y2 = g_kl2[base + n];
    __syncthreads();

    float* prow = pp + (size_t)(bh * 256 + qg0) * 256 + n;

    for (int q = 0; q < 8; q++) {
        const ulonglong2* qr2 = (const ulonglong2*)&qs[q * 64 + nh * 32];
        float x2 = q2s[q];

        // partial dot over this half (16 f32x2), 2 accumulators
        ull a0 = 0ull, a1 = 0ull;
#pragma unroll
        for (int i = 0; i < 8; i += 2) {
            ulonglong2 qa = qr2[i];
            ulonglong2 qb = qr2[i + 1];
            FMA2(a0, kr2[2 * i],     qa.x, a0);
            FMA2(a1, kr2[2 * i + 1], qa.y, a1);
            FMA2(a0, kr2[2 * i + 2], qb.x, a0);
            FMA2(a1, kr2[2 * i + 3], qb.y, a1);
        }
        float s0, s1, s2, s3;
        UPK2(s0, s1, a0); UPK2(s2, s3, a1);
        float xyp = (s0 + s1) + (s2 + s3);
        float xy = xyp + __shfl_xor_sync(0xffffffffu, xyp, 16);  // merge halves

        float A  = 1.f - 2.f * xy + y2;
        float Bc = 1.f - x2;
        float den = fmaxf(1.f - 2.f * xy + x2 * y2, 1e-15f);
        float ib = frcp(Bc);
        float r = A * ib;
        float fsc = den * ib;
        fsc *= fsc;                                  // (den/Bc)^2

        ull nr2;
        PK2(nr2, -r, -r);

        // partial sum 1/(k - r*q)^2 over this half; 4-way rcp combine
        float t0 = 0.f;
#pragma unroll
        for (int i = 0; i < 8; i++) {
            ulonglong2 qv = qr2[i];
            ull num, sqa, sqb, sv, pv;
            FMA2(num, nr2, qv.x, kr2[2 * i]);
            MUL2(sqa, num, num);
            FMA2(num, nr2, qv.y, kr2[2 * i + 1]);
            MUL2(sqb, num, num);
            ADD2(sv, sqa, sqb);
            MUL2(pv, sqa, sqb);
            float svl, svh, pvl, pvh;
            UPK2(svl, svh, sv);
            UPK2(pvl, pvh, pv);
            float num4 = fmaf(svl, pvh, svh * pvl);
            float den4 = fmaxf(pvl * pvh, 1e-37f);
            t0 = fmaf(num4, frcp(den4), t0);
        }
        float t0t = t0 + __shfl_xor_sync(0xffffffffu, t0, 16);   // merge halves

        float tacc = t0t * fsc;
        float tt = rsqrtf(tacc);
        // p = sigmoid(-2*artanh(clip(tt))) == (1 - min(tt, 1-1e-7)) / 2 exactly
        float p = 0.5f * (1.f - fminf(tt, 1.f - 1e-7f));
        if (nh == 0) prow[q * 256] = p;
    }
}

// ---------------- K4: midpoint as GEMM: nom = P @ GV, den = P @ (gamma-1) -----
// grid (4 qtiles of 64, 16 bh, 8 n-eighths), 256 threads, 4x4 register blocking.
__global__ __launch_bounds__(256) void midgemm_kernel(const float* __restrict__ pp)
{
    __shared__ __align__(16) float Ps[16][64];   // [n-step][q]
    __shared__ __align__(16) float Gs[16][64];   // [n-step][d]
    __shared__ float gms[16];                    // gamma-1 per n-step

    int qt = blockIdx.x, bh = blockIdx.y, ns = blockIdx.z;
    int t = threadIdx.x, tx = t & 15, ty = t >> 4;
    int base = bh * 256, nb = ns * 32;
    int row0 = bh * 256 + qt * 64;               // global q-row base

    int lr = t >> 2, lk = (t & 3) * 4;
    const float* pptr = pp + (size_t)(row0 + lr) * 256 + nb + lk;

    ull acc[4][2];
    float dacc[4] = {0.f, 0.f, 0.f, 0.f};
#pragma unroll
    for (int i = 0; i < 4; i++) { acc[i][0] = 0ull; acc[i][1] = 0ull; }

#pragma unroll
    for (int k0 = 0; k0 < 32; k0 += 16) {
        float4 pv = *(const float4*)(pptr + k0);
        Ps[lk + 0][lr] = pv.x; Ps[lk + 1][lr] = pv.y;
        Ps[lk + 2][lr] = pv.z; Ps[lk + 3][lr] = pv.w;
        float4 gvv = *(const float4*)&g_gv[(size_t)(base + nb + k0 + ty) * 64 + tx * 4];
        *(float4*)&Gs[ty][tx * 4] = gvv;
        if (t < 16) gms[t] = g_gamma[base + nb + k0 + t] - 1.f;
        __syncthreads();
#pragma unroll
        for (int kk = 0; kk < 16; kk++) {
            float4 a = *(const float4*)&Ps[kk][ty * 4];
            ulonglong2 bb = *(const ulonglong2*)&Gs[kk][tx * 4];
            float gm = gms[kk];
            ull aii;
            PK2(aii, a.x, a.x);
            FMA2(acc[0][0], aii, bb.x, acc[0][0]); FMA2(acc[0][1], aii, bb.y, acc[0][1]);
            PK2(aii, a.y, a.y);
            FMA2(acc[1][0], aii, bb.x, acc[1][0]); FMA2(acc[1][1], aii, bb.y, acc[1][1]);
            PK2(aii, a.z, a.z);
            FMA2(acc[2][0], aii, bb.x, acc[2][0]); FMA2(acc[2][1], aii, bb.y, acc[2][1]);
            PK2(aii, a.w, a.w);
            FMA2(acc[3][0], aii, bb.x, acc[3][0]); FMA2(acc[3][1], aii, bb.y, acc[3][1]);
            dacc[0] = fmaf(a.x, gm, dacc[0]);
            dacc[1] = fmaf(a.y, gm, dacc[1]);
            dacc[2] = fmaf(a.z, gm, dacc[2]);
            dacc[3] = fmaf(a.w, gm, dacc[3]);
        }
        __syncthreads();
    }

#pragma unroll
    for (int i = 0; i < 4; i++) {
        float4 v;
        UPK2(v.x, v.y, acc[i][0]);
        UPK2(v.z, v.w, acc[i][1]);
        float* prow = &g_part[ns][(size_t)(row0 + ty * 4 + i) * 68];
        *(float4*)&prow[tx * 4] = v;
        if (tx == 0) prow[64] = dacc[i];
    }
}

// ---------------- K5: combine partials + scalar_mul/logmap0 fused + out -------
__global__ __launch_bounds__(256) void finalize_kernel(float* __restrict__ out)
{
    __shared__ float sh[8];
    int q = blockIdx.x, b = blockIdx.y;
    int t = threadIdx.x, w = t >> 5, l = t & 31;

    size_t row = (size_t)((b * 8 + w) * 256 + q) * 68;

    float a0 = 0.f, a1 = 0.f, dn = 0.f;
#pragma unroll
    for (int i = 0; i < 8; i++) {
        const float* r = &g_part[i][row];
        ull m = *(const ull*)&r[2 * l];
        float x0, x1; UPK2(x0, x1, m);
        a0 += x0; a1 += x1;
        dn += r[64];
    }

    float sg = (dn >= 0.f) ? 1.f : -1.f;
    float dd = sg * fmaxf(fabsf(dn), 1e-10f);
    float y0 = __fdividef(a0, dd);
    float y1 = __fdividef(a1, dd);

    float nn2 = warp_sum(y0 * y0 + y1 * y1);
    float nm = fmaxf(sqrtf(nn2), 1e-15f);
    float f = 0.5f * artanh_pos(nm) / nm;   // fused scalar_mul(0.5)+logmap0(HD)
    float u0 = f * y0, u1 = f * y1;

    float us = f * f * nn2;                 // ||u||^2 for this head
    if (l == 0) sh[w] = us;
    __syncthreads();
    float tot = 0.f;
#pragma unroll
    for (int i = 0; i < 8; i++) tot += sh[i];
    float tn = fmaxf(sqrtf(tot), 1e-15f);
    float fs = tanhf(tn) / tn;              // expmap0 over HID

    float* orow = out + (q * 2 + b) * 512 + w * 64;
    ull ov; PK2(ov, fs * u0, fs * u1);
    *(ull*)&orow[2 * l] = ov;
}

// ---------------- launch ------------------------------------------------------
extern "C" void kernel_launch(void* const* d_in, const int* in_sizes, int n_in,
                              void* d_out, int out_size)
{
    const float* qin = (const float*)d_in[0];
    const float* Wq  = (const float*)d_in[1];
    const float* bq  = (const float*)d_in[2];
    const float* Wk  = (const float*)d_in[3];
    const float* bk  = (const float*)d_in[4];
    const float* Wv  = (const float*)d_in[5];
    const float* bv  = (const float*)d_in[6];
    float* out = (float*)d_out;

    const int ctx_elems  = S_ * B_ * HID_;        // 262144
    const int prob_elems = B_ * NH_ * S_ * S_;    // 1048576

    float* pp;
    if (out_size >= ctx_elems + prob_elems) {
        pp = out + ctx_elems;
    } else {
        void* sym = nullptr;
        cudaGetSymbolAddress(&sym, g_probs);
        pp = (float*)sym;
    }

    gemm_kernel<<<dim3(12, 8, 4), 256>>>(qin, Wq, Wk, Wv);
    postproc_kernel<<<dim3(64, 3), 256>>>(qin, bq, bk, bv);
    scores_kernel<<<dim3(32, 16, 2), 256>>>(pp);
    midgemm_kernel<<<dim3(4, 16, 8), 256>>>(pp);
    finalize_kernel<<<dim3(256, 2), 256>>>(out);
}